// round 13
// baseline (speedup 1.0000x reference)
#include <cuda_runtime.h>
#include <cuda_fp16.h>
#include <cstdint>

// ---------------------------------------------------------------------------
// VLMSpatialHead via mma.sync (HMMA fp16) on sm_103:
//   X   = hidden[flat_idx]              [N_TOK, 2048]
//   Hm  = mish(X @ W1^T + b1)           [N_TOK, 1024]
//   S   = Hm @ W2^T + b2                [N_TOK, 256]
//   out = segment_sum(S, segment_ids)   [N_IMG, 256]
// R11: revert R10's fused-gather loader (LDG in compute warps exposed global
//      latency -> regression); keep R9 cp.async structure + R10's
//      XOR-incremental ldmatrix addressing (alu 33% -> 14% measured).
// ---------------------------------------------------------------------------

#define NTOK_MAX 32768
#define HDIM     2048
#define DMID     1024
#define DOUT     256
#define PCHUNK   16

// ---------------- scratch (device globals; no allocs) ----------------
__device__ __align__(256) __half g_X  [(size_t)NTOK_MAX * HDIM];
__device__ __align__(256) __half g_W1h[(size_t)DMID * HDIM];
__device__ __align__(256) __half g_W2h[(size_t)DOUT * DMID];
__device__ __align__(256) __half g_H  [(size_t)NTOK_MAX * DMID];
__device__ __align__(256) float  g_S  [(size_t)NTOK_MAX * DOUT];
__device__ __align__(256) float  g_P  [64 * PCHUNK * DOUT];

// ---------------- helpers ----------------
__device__ __forceinline__ uint32_t smem_u32(const void* p) {
    uint32_t a;
    asm("{ .reg .u64 t; cvta.to.shared.u64 t, %1; cvt.u32.u64 %0, t; }" : "=r"(a) : "l"(p));
    return a;
}
__device__ __forceinline__ void cp16(uint32_t saddr, const void* gaddr) {
    asm volatile("cp.async.cg.shared.global [%0], [%1], 16;" :: "r"(saddr), "l"(gaddr));
}
#define CP_COMMIT() asm volatile("cp.async.commit_group;" ::: "memory")
#define CP_WAIT2()  asm volatile("cp.async.wait_group 2;"  ::: "memory")

#define LDSM4(r0, r1, r2, r3, a) \
    asm volatile("ldmatrix.sync.aligned.m8n8.x4.shared.b16 {%0,%1,%2,%3}, [%4];" \
                 : "=r"(r0), "=r"(r1), "=r"(r2), "=r"(r3) : "r"(a))

#define MMA16816(c, a, b) \
    asm volatile("mma.sync.aligned.m16n8k16.row.col.f32.f16.f16.f32 " \
                 "{%0,%1,%2,%3}, {%4,%5,%6,%7}, {%8,%9}, {%0,%1,%2,%3};" \
                 : "+f"((c)[0]), "+f"((c)[1]), "+f"((c)[2]), "+f"((c)[3]) \
                 : "r"((a)[0]), "r"((a)[1]), "r"((a)[2]), "r"((a)[3]), \
                   "r"((b)[0]), "r"((b)[1]))

__device__ __forceinline__ float mish_acc(float x) {
    float t = expf(fminf(x, 20.0f));
    float u = t * (t + 2.0f);
    return x * (u / (u + 2.0f));
}

// ---------------- fp32 -> fp16 convert (optional gather + pad) ----
__global__ void __launch_bounds__(256)
conv_fp16(const float* __restrict__ src, const int* __restrict__ gidx,
          int rows_valid, long long total4, int K, __half* __restrict__ dst)
{
    long long i = (long long)blockIdx.x * 256 + threadIdx.x;
    if (i >= total4) return;
    int k4 = K >> 2;
    int row = (int)(i / k4);
    int c   = (int)(i % k4);
    float4 v = make_float4(0.f, 0.f, 0.f, 0.f);
    if (row < rows_valid) {
        size_t srow = gidx ? (size_t)gidx[row] : (size_t)row;
        v = *(const float4*)(src + srow * (size_t)K + (size_t)c * 4);
    }
    __half2 h0 = __halves2half2(__float2half(v.x), __float2half(v.y));
    __half2 h1 = __halves2half2(__float2half(v.z), __float2half(v.w));
    uint2 hp;
    hp.x = *(uint32_t*)&h0; hp.y = *(uint32_t*)&h1;
    *(uint2*)(dst + i * 4) = hp;
}

// ---------------- HMMA GEMM: 128x256 CTA tile, BK=64, 4-stage ring ----
// Stage (48KB): [A 16K @0][W 32K @16384],
// A rows 128 x 128B, W rows 256 x 128B, SW128 swizzle (quad ^= row&7).
// LDSM addresses advance across k-steps by XOR 32/96 (swizzle-invariant).
#define STAGE_B   49152
#define GEMM_SMEM (4 * STAGE_B)

template<int KD, bool MISH>
__global__ void __launch_bounds__(512, 1)
mma_gemm(const __half* __restrict__ A, const __half* __restrict__ W,
         const float* __restrict__ bias,
         __half* __restrict__ OH, float* __restrict__ OF, int ldo)
{
    extern __shared__ __align__(128) char sm[];
    const uint32_t sbase = smem_u32(sm);
    const int tid  = threadIdx.x;
    const int lane = tid & 31;
    const int warp = tid >> 5;
    const int wm   = warp >> 2;   // 0..3 -> 32 rows each
    const int wn   = warp & 3;    // 0..3 -> 64 cols each
    const int bm   = blockIdx.y * 128;
    const int bn   = blockIdx.x * 256;

    constexpr int NCH = KD / 64;        // K chunks of 64 fp16 (128B)
    const int krow4   = KD / 8;         // row stride in uint4

    // ---- hoisted cp.async addressing: 6 chunks/thread/stage ----
    const uint4* gp[6];
    uint32_t     so[6];
    {
        #pragma unroll
        for (int it = 0; it < 2; it++) {          // A: 128 rows x 8 quads
            int e = tid + it * 512, r = e >> 3, q = e & 7;
            gp[it] = (const uint4*)A + (size_t)(bm + r) * krow4 + q;
            so[it] = (uint32_t)(r * 128 + ((q ^ (r & 7)) << 4));
        }
        #pragma unroll
        for (int it = 0; it < 4; it++) {          // W: 256 rows x 8 quads
            int e = tid + it * 512, r = e >> 3, q = e & 7;
            gp[2 + it] = (const uint4*)W + (size_t)(bn + r) * krow4 + q;
            so[2 + it] = (uint32_t)(16384 + r * 128 + ((q ^ (r & 7)) << 4));
        }
    }
    // ---- hoisted ldmatrix base addresses (relative to stage base) ----
    uint32_t aPre0, aPre1, bPre0, bPre1, bPre2, bPre3;
    {
        const int lh = lane >> 4;
        int r = wm * 32 + (lane & 15);
        aPre0 = (uint32_t)(r * 128 + ((lh ^ (r & 7)) << 4));
        r += 16;
        aPre1 = (uint32_t)(r * 128 + ((lh ^ (r & 7)) << 4));
        int rb = wn * 64 + (lane & 15);
        bPre0 = (uint32_t)(16384 + rb * 128 + ((lh ^ (rb & 7)) << 4));
        rb += 16;
        bPre1 = (uint32_t)(16384 + rb * 128 + ((lh ^ (rb & 7)) << 4));
        rb += 16;
        bPre2 = (uint32_t)(16384 + rb * 128 + ((lh ^ (rb & 7)) << 4));
        rb += 16;
        bPre3 = (uint32_t)(16384 + rb * 128 + ((lh ^ (rb & 7)) << 4));
    }

    float acc[2][8][4];
    #pragma unroll
    for (int i = 0; i < 2; i++)
        #pragma unroll
        for (int j = 0; j < 8; j++)
            #pragma unroll
            for (int k = 0; k < 4; k++) acc[i][j][k] = 0.0f;

    auto load_stage = [&](int ch) {
        uint32_t st = sbase + (uint32_t)(ch & 3) * STAGE_B;
        #pragma unroll
        for (int j = 0; j < 6; j++) cp16(st + so[j], gp[j] + ch * 8);
    };

    // prologue: 3 stages in flight
    load_stage(0);              CP_COMMIT();
    if (NCH > 1) load_stage(1); CP_COMMIT();
    if (NCH > 2) load_stage(2); CP_COMMIT();

    for (int i = 0; i < NCH; ++i) {
        CP_WAIT2();
        __syncthreads();
        int nxt = i + 3;
        if (nxt < NCH) load_stage(nxt);
        CP_COMMIT();

        const uint32_t st = sbase + (uint32_t)(i & 3) * STAGE_B;
        uint32_t aAd0 = st + aPre0, aAd1 = st + aPre1;
        uint32_t bAd0 = st + bPre0, bAd1 = st + bPre1;
        uint32_t bAd2 = st + bPre2, bAd3 = st + bPre3;

        #pragma unroll
        for (int ks = 0; ks < 4; ks++) {           // four K16 steps per chunk
            uint32_t ah[2][4];
            LDSM4(ah[0][0], ah[0][1], ah[0][2], ah[0][3], aAd0);
            LDSM4(ah[1][0], ah[1][1], ah[1][2], ah[1][3], aAd1);
            uint32_t bh[8][2];
            {
                uint32_t t0, t1, t2, t3;
                LDSM4(t0, t1, t2, t3, bAd0);
                bh[0][0]=t0; bh[1][0]=t1; bh[0][1]=t2; bh[1][1]=t3;
                LDSM4(t0, t1, t2, t3, bAd1);
                bh[2][0]=t0; bh[3][0]=t1; bh[2][1]=t2; bh[3][1]=t3;
                LDSM4(t0, t1, t2, t3, bAd2);
                bh[4][0]=t0; bh[5][0]=t1; bh[4][1]=t2; bh[5][1]=t3;
                LDSM4(t0, t1, t2, t3, bAd3);
                bh[6][0]=t0; bh[7][0]=t1; bh[6][1]=t2; bh[7][1]=t3;
            }
            #pragma unroll
            for (int mt = 0; mt < 2; mt++)
                #pragma unroll
                for (int nt = 0; nt < 8; nt++)
                    MMA16816(acc[mt][nt], ah[mt], bh[nt]);

            const uint32_t dx = (ks == 1) ? 96u : 32u;
            aAd0 ^= dx; aAd1 ^= dx;
            bAd0 ^= dx; bAd1 ^= dx; bAd2 ^= dx; bAd3 ^= dx;
        }
    }

    // -------- epilogue --------
    const int g  = lane >> 2;
    const int c2 = (lane & 3) * 2;
    #pragma unroll
    for (int nt = 0; nt < 8; nt++) {
        const int col = bn + wn * 64 + nt * 8 + c2;
        float2 bv = __ldg((const float2*)(bias + col));
        #pragma unroll
        for (int mt = 0; mt < 2; mt++) {
            const int row0 = bm + wm * 32 + mt * 16 + g;
            float v0 = acc[mt][nt][0] + bv.x;
            float v1 = acc[mt][nt][1] + bv.y;
            float v2 = acc[mt][nt][2] + bv.x;
            float v3 = acc[mt][nt][3] + bv.y;
            if (MISH) {
                v0 = mish_acc(v0); v1 = mish_acc(v1);
                v2 = mish_acc(v2); v3 = mish_acc(v3);
                __half2 hv0 = __halves2half2(__float2half(v0), __float2half(v1));
                __half2 hv1 = __halves2half2(__float2half(v2), __float2half(v3));
                *(__half2*)(OH + (size_t)row0 * ldo + col)       = hv0;
                *(__half2*)(OH + (size_t)(row0 + 8) * ldo + col) = hv1;
            } else {
                *(float2*)(OF + (size_t)row0 * ldo + col)       = make_float2(v0, v1);
                *(float2*)(OF + (size_t)(row0 + 8) * ldo + col) = make_float2(v2, v3);
            }
        }
    }
}

// ---------------- deterministic 2-phase segment pooling ----------------
__global__ void __launch_bounds__(1024)
pool_partial(const float* __restrict__ S, const int* __restrict__ seg,
             int n_tok, float* __restrict__ P)
{
    const int gseg = blockIdx.x;
    const int sub  = threadIdx.x >> 8;
    const int col  = threadIdx.x & 255;
    const int chunk = blockIdx.y * 4 + sub;

    int lo = 0, hi = n_tok;
    while (lo < hi) { int m = (lo + hi) >> 1; if (seg[m] < gseg) lo = m + 1; else hi = m; }
    const int s = lo;
    lo = s; hi = n_tok;
    while (lo < hi) { int m = (lo + hi) >> 1; if (seg[m] < gseg + 1) lo = m + 1; else hi = m; }
    const int e = lo;

    const int len = e - s;
    const int L = (len + PCHUNK - 1) / PCHUNK;
    const int cs = s + chunk * L;
    const int ce = min(cs + L, e);

    float a0 = 0.f, a1 = 0.f, a2 = 0.f, a3 = 0.f;
    int t = cs;
    for (; t + 4 <= ce; t += 4) {
        a0 += S[(size_t)(t + 0) * DOUT + col];
        a1 += S[(size_t)(t + 1) * DOUT + col];
        a2 += S[(size_t)(t + 2) * DOUT + col];
        a3 += S[(size_t)(t + 3) * DOUT + col];
    }
    float acc = (a0 + a1) + (a2 + a3);
    for (; t < ce; t++) acc += S[(size_t)t * DOUT + col];
    P[((size_t)gseg * PCHUNK + chunk) * DOUT + col] = acc;
}

__global__ void __launch_bounds__(256)
pool_final(const float* __restrict__ P, float* __restrict__ out)
{
    const int gseg = blockIdx.x, col = threadIdx.x;
    float acc = 0.f;
    #pragma unroll
    for (int c = 0; c < PCHUNK; c++)
        acc += P[((size_t)gseg * PCHUNK + c) * DOUT + col];
    out[(size_t)gseg * DOUT + col] = acc;
}

// ---------------- launch ----------------
extern "C" void kernel_launch(void* const* d_in, const int* in_sizes, int n_in,
                              void* d_out, int out_size)
{
    const float* hidden   = (const float*)d_in[0];
    const float* W1       = (const float*)d_in[1];
    const float* b1       = (const float*)d_in[2];
    const float* W2       = (const float*)d_in[3];
    const float* b2       = (const float*)d_in[4];
    const int*   flat_idx = (const int*)d_in[5];
    const int*   seg      = (const int*)d_in[6];
    float*       out      = (float*)d_out;

    const int n_tok = in_sizes[5];
    const int n_img = out_size / DOUT;
    const int mpad  = ((n_tok + 127) / 128) * 128;

    __half *xh, *w1h, *w2h, *hh;
    float *sbuf, *pbuf;
    cudaGetSymbolAddress((void**)&xh,  g_X);
    cudaGetSymbolAddress((void**)&w1h, g_W1h);
    cudaGetSymbolAddress((void**)&w2h, g_W2h);
    cudaGetSymbolAddress((void**)&hh,  g_H);
    cudaGetSymbolAddress((void**)&sbuf, g_S);
    cudaGetSymbolAddress((void**)&pbuf, g_P);

    cudaFuncSetAttribute(mma_gemm<HDIM, true>,
                         cudaFuncAttributeMaxDynamicSharedMemorySize, GEMM_SMEM);
    cudaFuncSetAttribute(mma_gemm<DMID, false>,
                         cudaFuncAttributeMaxDynamicSharedMemorySize, GEMM_SMEM);

    // 1) conversions
    {
        long long t4 = (long long)mpad * HDIM / 4;
        conv_fp16<<<(unsigned)((t4 + 255) / 256), 256>>>(hidden, flat_idx, n_tok, t4, HDIM, xh);
        long long w1t = (long long)DMID * HDIM / 4;
        conv_fp16<<<(unsigned)((w1t + 255) / 256), 256>>>(W1, nullptr, DMID, w1t, HDIM, w1h);
        long long w2t = (long long)DOUT * DMID / 4;
        conv_fp16<<<(unsigned)((w2t + 255) / 256), 256>>>(W2, nullptr, DOUT, w2t, DMID, w2h);
    }
    // 2) GEMM1 + bias + mish -> H (fp16)
    {
        dim3 g(DMID / 256, mpad / 128);
        mma_gemm<HDIM, true><<<g, 512, GEMM_SMEM>>>(xh, w1h, b1, hh, nullptr, DMID);
    }
    // 3) GEMM2 + bias -> S (fp32)
    {
        dim3 g(DOUT / 256, mpad / 128);
        mma_gemm<DMID, false><<<g, 512, GEMM_SMEM>>>(hh, w2h, b2, nullptr, sbuf, DOUT);
    }
    // 4) pooling (2-phase deterministic)
    {
        dim3 gp(n_img, PCHUNK / 4);
        pool_partial<<<gp, 1024>>>(sbuf, seg, n_tok, pbuf);
        pool_final<<<n_img, 256>>>(pbuf, out);
    }
}

// round 14
// speedup vs baseline: 1.0006x; 1.0006x over previous
#include <cuda_runtime.h>
#include <cuda_fp16.h>
#include <cstdint>

// ---------------------------------------------------------------------------
// VLMSpatialHead via mma.sync (HMMA fp16) on sm_103:
//   X   = hidden[flat_idx]              [N_TOK, 2048]
//   Hm  = mish(X @ W1^T + b1)           [N_TOK, 1024]
//   S   = Hm @ W2^T + b2                [N_TOK, 256]
//   out = segment_sum(S, segment_ids)   [N_IMG, 256]
// R11: revert R10's fused-gather loader (LDG in compute warps exposed global
//      latency -> regression); keep R9 cp.async structure + R10's
//      XOR-incremental ldmatrix addressing (alu 33% -> 14% measured).
// ---------------------------------------------------------------------------

#define NTOK_MAX 32768
#define HDIM     2048
#define DMID     1024
#define DOUT     256
#define PCHUNK   16

// ---------------- scratch (device globals; no allocs) ----------------
__device__ __align__(256) __half g_X  [(size_t)NTOK_MAX * HDIM];
__device__ __align__(256) __half g_W1h[(size_t)DMID * HDIM];
__device__ __align__(256) __half g_W2h[(size_t)DOUT * DMID];
__device__ __align__(256) __half g_H  [(size_t)NTOK_MAX * DMID];
__device__ __align__(256) float  g_S  [(size_t)NTOK_MAX * DOUT];
__device__ __align__(256) float  g_P  [64 * PCHUNK * DOUT];

// ---------------- helpers ----------------
__device__ __forceinline__ uint32_t smem_u32(const void* p) {
    uint32_t a;
    asm("{ .reg .u64 t; cvta.to.shared.u64 t, %1; cvt.u32.u64 %0, t; }" : "=r"(a) : "l"(p));
    return a;
}
__device__ __forceinline__ void cp16(uint32_t saddr, const void* gaddr) {
    asm volatile("cp.async.cg.shared.global [%0], [%1], 16;" :: "r"(saddr), "l"(gaddr));
}
#define CP_COMMIT() asm volatile("cp.async.commit_group;" ::: "memory")
#define CP_WAIT2()  asm volatile("cp.async.wait_group 2;"  ::: "memory")

#define LDSM4(r0, r1, r2, r3, a) \
    asm volatile("ldmatrix.sync.aligned.m8n8.x4.shared.b16 {%0,%1,%2,%3}, [%4];" \
                 : "=r"(r0), "=r"(r1), "=r"(r2), "=r"(r3) : "r"(a))

#define MMA16816(c, a, b) \
    asm volatile("mma.sync.aligned.m16n8k16.row.col.f32.f16.f16.f32 " \
                 "{%0,%1,%2,%3}, {%4,%5,%6,%7}, {%8,%9}, {%0,%1,%2,%3};" \
                 : "+f"((c)[0]), "+f"((c)[1]), "+f"((c)[2]), "+f"((c)[3]) \
                 : "r"((a)[0]), "r"((a)[1]), "r"((a)[2]), "r"((a)[3]), \
                   "r"((b)[0]), "r"((b)[1]))

__device__ __forceinline__ float mish_acc(float x) {
    float t = expf(fminf(x, 20.0f));
    float u = t * (t + 2.0f);
    return x * (u / (u + 2.0f));
}

// ---------------- fp32 -> fp16 convert (optional gather + pad) ----
__global__ void __launch_bounds__(256)
conv_fp16(const float* __restrict__ src, const int* __restrict__ gidx,
          int rows_valid, long long total4, int K, __half* __restrict__ dst)
{
    long long i = (long long)blockIdx.x * 256 + threadIdx.x;
    if (i >= total4) return;
    int k4 = K >> 2;
    int row = (int)(i / k4);
    int c   = (int)(i % k4);
    float4 v = make_float4(0.f, 0.f, 0.f, 0.f);
    if (row < rows_valid) {
        size_t srow = gidx ? (size_t)gidx[row] : (size_t)row;
        v = *(const float4*)(src + srow * (size_t)K + (size_t)c * 4);
    }
    __half2 h0 = __halves2half2(__float2half(v.x), __float2half(v.y));
    __half2 h1 = __halves2half2(__float2half(v.z), __float2half(v.w));
    uint2 hp;
    hp.x = *(uint32_t*)&h0; hp.y = *(uint32_t*)&h1;
    *(uint2*)(dst + i * 4) = hp;
}

// ---------------- HMMA GEMM: 128x256 CTA tile, BK=64, 4-stage ring ----
// Stage (48KB): [A 16K @0][W 32K @16384],
// A rows 128 x 128B, W rows 256 x 128B, SW128 swizzle (quad ^= row&7).
// LDSM addresses advance across k-steps by XOR 32/96 (swizzle-invariant).
#define STAGE_B   49152
#define GEMM_SMEM (4 * STAGE_B)

template<int KD, bool MISH>
__global__ void __launch_bounds__(512, 1)
mma_gemm(const __half* __restrict__ A, const __half* __restrict__ W,
         const float* __restrict__ bias,
         __half* __restrict__ OH, float* __restrict__ OF, int ldo)
{
    extern __shared__ __align__(128) char sm[];
    const uint32_t sbase = smem_u32(sm);
    const int tid  = threadIdx.x;
    const int lane = tid & 31;
    const int warp = tid >> 5;
    const int wm   = warp >> 2;   // 0..3 -> 32 rows each
    const int wn   = warp & 3;    // 0..3 -> 64 cols each
    const int bm   = blockIdx.y * 128;
    const int bn   = blockIdx.x * 256;

    constexpr int NCH = KD / 64;        // K chunks of 64 fp16 (128B)
    const int krow4   = KD / 8;         // row stride in uint4

    // ---- hoisted cp.async addressing: 6 chunks/thread/stage ----
    const uint4* gp[6];
    uint32_t     so[6];
    {
        #pragma unroll
        for (int it = 0; it < 2; it++) {          // A: 128 rows x 8 quads
            int e = tid + it * 512, r = e >> 3, q = e & 7;
            gp[it] = (const uint4*)A + (size_t)(bm + r) * krow4 + q;
            so[it] = (uint32_t)(r * 128 + ((q ^ (r & 7)) << 4));
        }
        #pragma unroll
        for (int it = 0; it < 4; it++) {          // W: 256 rows x 8 quads
            int e = tid + it * 512, r = e >> 3, q = e & 7;
            gp[2 + it] = (const uint4*)W + (size_t)(bn + r) * krow4 + q;
            so[2 + it] = (uint32_t)(16384 + r * 128 + ((q ^ (r & 7)) << 4));
        }
    }
    // ---- hoisted ldmatrix base addresses (relative to stage base) ----
    uint32_t aPre0, aPre1, bPre0, bPre1, bPre2, bPre3;
    {
        const int lh = lane >> 4;
        int r = wm * 32 + (lane & 15);
        aPre0 = (uint32_t)(r * 128 + ((lh ^ (r & 7)) << 4));
        r += 16;
        aPre1 = (uint32_t)(r * 128 + ((lh ^ (r & 7)) << 4));
        int rb = wn * 64 + (lane & 15);
        bPre0 = (uint32_t)(16384 + rb * 128 + ((lh ^ (rb & 7)) << 4));
        rb += 16;
        bPre1 = (uint32_t)(16384 + rb * 128 + ((lh ^ (rb & 7)) << 4));
        rb += 16;
        bPre2 = (uint32_t)(16384 + rb * 128 + ((lh ^ (rb & 7)) << 4));
        rb += 16;
        bPre3 = (uint32_t)(16384 + rb * 128 + ((lh ^ (rb & 7)) << 4));
    }

    float acc[2][8][4];
    #pragma unroll
    for (int i = 0; i < 2; i++)
        #pragma unroll
        for (int j = 0; j < 8; j++)
            #pragma unroll
            for (int k = 0; k < 4; k++) acc[i][j][k] = 0.0f;

    auto load_stage = [&](int ch) {
        uint32_t st = sbase + (uint32_t)(ch & 3) * STAGE_B;
        #pragma unroll
        for (int j = 0; j < 6; j++) cp16(st + so[j], gp[j] + ch * 8);
    };

    // prologue: 3 stages in flight
    load_stage(0);              CP_COMMIT();
    if (NCH > 1) load_stage(1); CP_COMMIT();
    if (NCH > 2) load_stage(2); CP_COMMIT();

    for (int i = 0; i < NCH; ++i) {
        CP_WAIT2();
        __syncthreads();
        int nxt = i + 3;
        if (nxt < NCH) load_stage(nxt);
        CP_COMMIT();

        const uint32_t st = sbase + (uint32_t)(i & 3) * STAGE_B;
        uint32_t aAd0 = st + aPre0, aAd1 = st + aPre1;
        uint32_t bAd0 = st + bPre0, bAd1 = st + bPre1;
        uint32_t bAd2 = st + bPre2, bAd3 = st + bPre3;

        #pragma unroll
        for (int ks = 0; ks < 4; ks++) {           // four K16 steps per chunk
            uint32_t ah[2][4];
            LDSM4(ah[0][0], ah[0][1], ah[0][2], ah[0][3], aAd0);
            LDSM4(ah[1][0], ah[1][1], ah[1][2], ah[1][3], aAd1);
            uint32_t bh[8][2];
            {
                uint32_t t0, t1, t2, t3;
                LDSM4(t0, t1, t2, t3, bAd0);
                bh[0][0]=t0; bh[1][0]=t1; bh[0][1]=t2; bh[1][1]=t3;
                LDSM4(t0, t1, t2, t3, bAd1);
                bh[2][0]=t0; bh[3][0]=t1; bh[2][1]=t2; bh[3][1]=t3;
                LDSM4(t0, t1, t2, t3, bAd2);
                bh[4][0]=t0; bh[5][0]=t1; bh[4][1]=t2; bh[5][1]=t3;
                LDSM4(t0, t1, t2, t3, bAd3);
                bh[6][0]=t0; bh[7][0]=t1; bh[6][1]=t2; bh[7][1]=t3;
            }
            #pragma unroll
            for (int mt = 0; mt < 2; mt++)
                #pragma unroll
                for (int nt = 0; nt < 8; nt++)
                    MMA16816(acc[mt][nt], ah[mt], bh[nt]);

            const uint32_t dx = (ks == 1) ? 96u : 32u;
            aAd0 ^= dx; aAd1 ^= dx;
            bAd0 ^= dx; bAd1 ^= dx; bAd2 ^= dx; bAd3 ^= dx;
        }
    }

    // -------- epilogue --------
    const int g  = lane >> 2;
    const int c2 = (lane & 3) * 2;
    #pragma unroll
    for (int nt = 0; nt < 8; nt++) {
        const int col = bn + wn * 64 + nt * 8 + c2;
        float2 bv = __ldg((const float2*)(bias + col));
        #pragma unroll
        for (int mt = 0; mt < 2; mt++) {
            const int row0 = bm + wm * 32 + mt * 16 + g;
            float v0 = acc[mt][nt][0] + bv.x;
            float v1 = acc[mt][nt][1] + bv.y;
            float v2 = acc[mt][nt][2] + bv.x;
            float v3 = acc[mt][nt][3] + bv.y;
            if (MISH) {
                v0 = mish_acc(v0); v1 = mish_acc(v1);
                v2 = mish_acc(v2); v3 = mish_acc(v3);
                __half2 hv0 = __halves2half2(__float2half(v0), __float2half(v1));
                __half2 hv1 = __halves2half2(__float2half(v2), __float2half(v3));
                *(__half2*)(OH + (size_t)row0 * ldo + col)       = hv0;
                *(__half2*)(OH + (size_t)(row0 + 8) * ldo + col) = hv1;
            } else {
                *(float2*)(OF + (size_t)row0 * ldo + col)       = make_float2(v0, v1);
                *(float2*)(OF + (size_t)(row0 + 8) * ldo + col) = make_float2(v2, v3);
            }
        }
    }
}

// ---------------- deterministic 2-phase segment pooling ----------------
__global__ void __launch_bounds__(1024)
pool_partial(const float* __restrict__ S, const int* __restrict__ seg,
             int n_tok, float* __restrict__ P)
{
    const int gseg = blockIdx.x;
    const int sub  = threadIdx.x >> 8;
    const int col  = threadIdx.x & 255;
    const int chunk = blockIdx.y * 4 + sub;

    int lo = 0, hi = n_tok;
    while (lo < hi) { int m = (lo + hi) >> 1; if (seg[m] < gseg) lo = m + 1; else hi = m; }
    const int s = lo;
    lo = s; hi = n_tok;
    while (lo < hi) { int m = (lo + hi) >> 1; if (seg[m] < gseg + 1) lo = m + 1; else hi = m; }
    const int e = lo;

    const int len = e - s;
    const int L = (len + PCHUNK - 1) / PCHUNK;
    const int cs = s + chunk * L;
    const int ce = min(cs + L, e);

    float a0 = 0.f, a1 = 0.f, a2 = 0.f, a3 = 0.f;
    int t = cs;
    for (; t + 4 <= ce; t += 4) {
        a0 += S[(size_t)(t + 0) * DOUT + col];
        a1 += S[(size_t)(t + 1) * DOUT + col];
        a2 += S[(size_t)(t + 2) * DOUT + col];
        a3 += S[(size_t)(t + 3) * DOUT + col];
    }
    float acc = (a0 + a1) + (a2 + a3);
    for (; t < ce; t++) acc += S[(size_t)t * DOUT + col];
    P[((size_t)gseg * PCHUNK + chunk) * DOUT + col] = acc;
}

__global__ void __launch_bounds__(256)
pool_final(const float* __restrict__ P, float* __restrict__ out)
{
    const int gseg = blockIdx.x, col = threadIdx.x;
    float acc = 0.f;
    #pragma unroll
    for (int c = 0; c < PCHUNK; c++)
        acc += P[((size_t)gseg * PCHUNK + c) * DOUT + col];
    out[(size_t)gseg * DOUT + col] = acc;
}

// ---------------- launch ----------------
extern "C" void kernel_launch(void* const* d_in, const int* in_sizes, int n_in,
                              void* d_out, int out_size)
{
    const float* hidden   = (const float*)d_in[0];
    const float* W1       = (const float*)d_in[1];
    const float* b1       = (const float*)d_in[2];
    const float* W2       = (const float*)d_in[3];
    const float* b2       = (const float*)d_in[4];
    const int*   flat_idx = (const int*)d_in[5];
    const int*   seg      = (const int*)d_in[6];
    float*       out      = (float*)d_out;

    const int n_tok = in_sizes[5];
    const int n_img = out_size / DOUT;
    const int mpad  = ((n_tok + 127) / 128) * 128;

    __half *xh, *w1h, *w2h, *hh;
    float *sbuf, *pbuf;
    cudaGetSymbolAddress((void**)&xh,  g_X);
    cudaGetSymbolAddress((void**)&w1h, g_W1h);
    cudaGetSymbolAddress((void**)&w2h, g_W2h);
    cudaGetSymbolAddress((void**)&hh,  g_H);
    cudaGetSymbolAddress((void**)&sbuf, g_S);
    cudaGetSymbolAddress((void**)&pbuf, g_P);

    cudaFuncSetAttribute(mma_gemm<HDIM, true>,
                         cudaFuncAttributeMaxDynamicSharedMemorySize, GEMM_SMEM);
    cudaFuncSetAttribute(mma_gemm<DMID, false>,
                         cudaFuncAttributeMaxDynamicSharedMemorySize, GEMM_SMEM);

    // 1) conversions
    {
        long long t4 = (long long)mpad * HDIM / 4;
        conv_fp16<<<(unsigned)((t4 + 255) / 256), 256>>>(hidden, flat_idx, n_tok, t4, HDIM, xh);
        long long w1t = (long long)DMID * HDIM / 4;
        conv_fp16<<<(unsigned)((w1t + 255) / 256), 256>>>(W1, nullptr, DMID, w1t, HDIM, w1h);
        long long w2t = (long long)DOUT * DMID / 4;
        conv_fp16<<<(unsigned)((w2t + 255) / 256), 256>>>(W2, nullptr, DOUT, w2t, DMID, w2h);
    }
    // 2) GEMM1 + bias + mish -> H (fp16)
    {
        dim3 g(DMID / 256, mpad / 128);
        mma_gemm<HDIM, true><<<g, 512, GEMM_SMEM>>>(xh, w1h, b1, hh, nullptr, DMID);
    }
    // 3) GEMM2 + bias -> S (fp32)
    {
        dim3 g(DOUT / 256, mpad / 128);
        mma_gemm<DMID, false><<<g, 512, GEMM_SMEM>>>(hh, w2h, b2, nullptr, sbuf, DOUT);
    }
    // 4) pooling (2-phase deterministic)
    {
        dim3 gp(n_img, PCHUNK / 4);
        pool_partial<<<gp, 1024>>>(sbuf, seg, n_tok, pbuf);
        pool_final<<<n_img, 256>>>(pbuf, out);
    }
}

// round 15
// speedup vs baseline: 1.0017x; 1.0011x over previous
#include <cuda_runtime.h>
#include <cuda_fp16.h>
#include <cstdint>

// ---------------------------------------------------------------------------
// VLMSpatialHead via mma.sync (HMMA fp16) on sm_103:
//   X   = hidden[flat_idx]              [N_TOK, 2048]
//   Hm  = mish(X @ W1^T + b1)           [N_TOK, 1024]
//   S   = Hm @ W2^T + b2                [N_TOK, 256]
//   out = segment_sum(S, segment_ids)   [N_IMG, 256]
// R11: revert R10's fused-gather loader (LDG in compute warps exposed global
//      latency -> regression); keep R9 cp.async structure + R10's
//      XOR-incremental ldmatrix addressing (alu 33% -> 14% measured).
// ---------------------------------------------------------------------------

#define NTOK_MAX 32768
#define HDIM     2048
#define DMID     1024
#define DOUT     256
#define PCHUNK   16

// ---------------- scratch (device globals; no allocs) ----------------
__device__ __align__(256) __half g_X  [(size_t)NTOK_MAX * HDIM];
__device__ __align__(256) __half g_W1h[(size_t)DMID * HDIM];
__device__ __align__(256) __half g_W2h[(size_t)DOUT * DMID];
__device__ __align__(256) __half g_H  [(size_t)NTOK_MAX * DMID];
__device__ __align__(256) float  g_S  [(size_t)NTOK_MAX * DOUT];
__device__ __align__(256) float  g_P  [64 * PCHUNK * DOUT];

// ---------------- helpers ----------------
__device__ __forceinline__ uint32_t smem_u32(const void* p) {
    uint32_t a;
    asm("{ .reg .u64 t; cvta.to.shared.u64 t, %1; cvt.u32.u64 %0, t; }" : "=r"(a) : "l"(p));
    return a;
}
__device__ __forceinline__ void cp16(uint32_t saddr, const void* gaddr) {
    asm volatile("cp.async.cg.shared.global [%0], [%1], 16;" :: "r"(saddr), "l"(gaddr));
}
#define CP_COMMIT() asm volatile("cp.async.commit_group;" ::: "memory")
#define CP_WAIT2()  asm volatile("cp.async.wait_group 2;"  ::: "memory")

#define LDSM4(r0, r1, r2, r3, a) \
    asm volatile("ldmatrix.sync.aligned.m8n8.x4.shared.b16 {%0,%1,%2,%3}, [%4];" \
                 : "=r"(r0), "=r"(r1), "=r"(r2), "=r"(r3) : "r"(a))

#define MMA16816(c, a, b) \
    asm volatile("mma.sync.aligned.m16n8k16.row.col.f32.f16.f16.f32 " \
                 "{%0,%1,%2,%3}, {%4,%5,%6,%7}, {%8,%9}, {%0,%1,%2,%3};" \
                 : "+f"((c)[0]), "+f"((c)[1]), "+f"((c)[2]), "+f"((c)[3]) \
                 : "r"((a)[0]), "r"((a)[1]), "r"((a)[2]), "r"((a)[3]), \
                   "r"((b)[0]), "r"((b)[1]))

__device__ __forceinline__ float mish_acc(float x) {
    float t = expf(fminf(x, 20.0f));
    float u = t * (t + 2.0f);
    return x * (u / (u + 2.0f));
}

// ---------------- fp32 -> fp16 convert (optional gather + pad) ----
__global__ void __launch_bounds__(256)
conv_fp16(const float* __restrict__ src, const int* __restrict__ gidx,
          int rows_valid, long long total4, int K, __half* __restrict__ dst)
{
    long long i = (long long)blockIdx.x * 256 + threadIdx.x;
    if (i >= total4) return;
    int k4 = K >> 2;
    int row = (int)(i / k4);
    int c   = (int)(i % k4);
    float4 v = make_float4(0.f, 0.f, 0.f, 0.f);
    if (row < rows_valid) {
        size_t srow = gidx ? (size_t)gidx[row] : (size_t)row;
        v = *(const float4*)(src + srow * (size_t)K + (size_t)c * 4);
    }
    __half2 h0 = __halves2half2(__float2half(v.x), __float2half(v.y));
    __half2 h1 = __halves2half2(__float2half(v.z), __float2half(v.w));
    uint2 hp;
    hp.x = *(uint32_t*)&h0; hp.y = *(uint32_t*)&h1;
    *(uint2*)(dst + i * 4) = hp;
}

// ---------------- HMMA GEMM: 128x256 CTA tile, BK=64, 4-stage ring ----
// Stage (48KB): [A 16K @0][W 32K @16384],
// A rows 128 x 128B, W rows 256 x 128B, SW128 swizzle (quad ^= row&7).
// LDSM addresses advance across k-steps by XOR 32/96 (swizzle-invariant).
#define STAGE_B   49152
#define GEMM_SMEM (4 * STAGE_B)

template<int KD, bool MISH>
__global__ void __launch_bounds__(512, 1)
mma_gemm(const __half* __restrict__ A, const __half* __restrict__ W,
         const float* __restrict__ bias,
         __half* __restrict__ OH, float* __restrict__ OF, int ldo)
{
    extern __shared__ __align__(128) char sm[];
    const uint32_t sbase = smem_u32(sm);
    const int tid  = threadIdx.x;
    const int lane = tid & 31;
    const int warp = tid >> 5;
    const int wm   = warp >> 2;   // 0..3 -> 32 rows each
    const int wn   = warp & 3;    // 0..3 -> 64 cols each
    const int bm   = blockIdx.y * 128;
    const int bn   = blockIdx.x * 256;

    constexpr int NCH = KD / 64;        // K chunks of 64 fp16 (128B)
    const int krow4   = KD / 8;         // row stride in uint4

    // ---- hoisted cp.async addressing: 6 chunks/thread/stage ----
    const uint4* gp[6];
    uint32_t     so[6];
    {
        #pragma unroll
        for (int it = 0; it < 2; it++) {          // A: 128 rows x 8 quads
            int e = tid + it * 512, r = e >> 3, q = e & 7;
            gp[it] = (const uint4*)A + (size_t)(bm + r) * krow4 + q;
            so[it] = (uint32_t)(r * 128 + ((q ^ (r & 7)) << 4));
        }
        #pragma unroll
        for (int it = 0; it < 4; it++) {          // W: 256 rows x 8 quads
            int e = tid + it * 512, r = e >> 3, q = e & 7;
            gp[2 + it] = (const uint4*)W + (size_t)(bn + r) * krow4 + q;
            so[2 + it] = (uint32_t)(16384 + r * 128 + ((q ^ (r & 7)) << 4));
        }
    }
    // ---- hoisted ldmatrix base addresses (relative to stage base) ----
    uint32_t aPre0, aPre1, bPre0, bPre1, bPre2, bPre3;
    {
        const int lh = lane >> 4;
        int r = wm * 32 + (lane & 15);
        aPre0 = (uint32_t)(r * 128 + ((lh ^ (r & 7)) << 4));
        r += 16;
        aPre1 = (uint32_t)(r * 128 + ((lh ^ (r & 7)) << 4));
        int rb = wn * 64 + (lane & 15);
        bPre0 = (uint32_t)(16384 + rb * 128 + ((lh ^ (rb & 7)) << 4));
        rb += 16;
        bPre1 = (uint32_t)(16384 + rb * 128 + ((lh ^ (rb & 7)) << 4));
        rb += 16;
        bPre2 = (uint32_t)(16384 + rb * 128 + ((lh ^ (rb & 7)) << 4));
        rb += 16;
        bPre3 = (uint32_t)(16384 + rb * 128 + ((lh ^ (rb & 7)) << 4));
    }

    float acc[2][8][4];
    #pragma unroll
    for (int i = 0; i < 2; i++)
        #pragma unroll
        for (int j = 0; j < 8; j++)
            #pragma unroll
            for (int k = 0; k < 4; k++) acc[i][j][k] = 0.0f;

    auto load_stage = [&](int ch) {
        uint32_t st = sbase + (uint32_t)(ch & 3) * STAGE_B;
        #pragma unroll
        for (int j = 0; j < 6; j++) cp16(st + so[j], gp[j] + ch * 8);
    };

    // prologue: 3 stages in flight
    load_stage(0);              CP_COMMIT();
    if (NCH > 1) load_stage(1); CP_COMMIT();
    if (NCH > 2) load_stage(2); CP_COMMIT();

    for (int i = 0; i < NCH; ++i) {
        CP_WAIT2();
        __syncthreads();
        int nxt = i + 3;
        if (nxt < NCH) load_stage(nxt);
        CP_COMMIT();

        const uint32_t st = sbase + (uint32_t)(i & 3) * STAGE_B;
        uint32_t aAd0 = st + aPre0, aAd1 = st + aPre1;
        uint32_t bAd0 = st + bPre0, bAd1 = st + bPre1;
        uint32_t bAd2 = st + bPre2, bAd3 = st + bPre3;

        #pragma unroll
        for (int ks = 0; ks < 4; ks++) {           // four K16 steps per chunk
            uint32_t ah[2][4];
            LDSM4(ah[0][0], ah[0][1], ah[0][2], ah[0][3], aAd0);
            LDSM4(ah[1][0], ah[1][1], ah[1][2], ah[1][3], aAd1);
            uint32_t bh[8][2];
            {
                uint32_t t0, t1, t2, t3;
                LDSM4(t0, t1, t2, t3, bAd0);
                bh[0][0]=t0; bh[1][0]=t1; bh[0][1]=t2; bh[1][1]=t3;
                LDSM4(t0, t1, t2, t3, bAd1);
                bh[2][0]=t0; bh[3][0]=t1; bh[2][1]=t2; bh[3][1]=t3;
                LDSM4(t0, t1, t2, t3, bAd2);
                bh[4][0]=t0; bh[5][0]=t1; bh[4][1]=t2; bh[5][1]=t3;
                LDSM4(t0, t1, t2, t3, bAd3);
                bh[6][0]=t0; bh[7][0]=t1; bh[6][1]=t2; bh[7][1]=t3;
            }
            #pragma unroll
            for (int mt = 0; mt < 2; mt++)
                #pragma unroll
                for (int nt = 0; nt < 8; nt++)
                    MMA16816(acc[mt][nt], ah[mt], bh[nt]);

            const uint32_t dx = (ks == 1) ? 96u : 32u;
            aAd0 ^= dx; aAd1 ^= dx;
            bAd0 ^= dx; bAd1 ^= dx; bAd2 ^= dx; bAd3 ^= dx;
        }
    }

    // -------- epilogue --------
    const int g  = lane >> 2;
    const int c2 = (lane & 3) * 2;
    #pragma unroll
    for (int nt = 0; nt < 8; nt++) {
        const int col = bn + wn * 64 + nt * 8 + c2;
        float2 bv = __ldg((const float2*)(bias + col));
        #pragma unroll
        for (int mt = 0; mt < 2; mt++) {
            const int row0 = bm + wm * 32 + mt * 16 + g;
            float v0 = acc[mt][nt][0] + bv.x;
            float v1 = acc[mt][nt][1] + bv.y;
            float v2 = acc[mt][nt][2] + bv.x;
            float v3 = acc[mt][nt][3] + bv.y;
            if (MISH) {
                v0 = mish_acc(v0); v1 = mish_acc(v1);
                v2 = mish_acc(v2); v3 = mish_acc(v3);
                __half2 hv0 = __halves2half2(__float2half(v0), __float2half(v1));
                __half2 hv1 = __halves2half2(__float2half(v2), __float2half(v3));
                *(__half2*)(OH + (size_t)row0 * ldo + col)       = hv0;
                *(__half2*)(OH + (size_t)(row0 + 8) * ldo + col) = hv1;
            } else {
                *(float2*)(OF + (size_t)row0 * ldo + col)       = make_float2(v0, v1);
                *(float2*)(OF + (size_t)(row0 + 8) * ldo + col) = make_float2(v2, v3);
            }
        }
    }
}

// ---------------- deterministic 2-phase segment pooling ----------------
__global__ void __launch_bounds__(1024)
pool_partial(const float* __restrict__ S, const int* __restrict__ seg,
             int n_tok, float* __restrict__ P)
{
    const int gseg = blockIdx.x;
    const int sub  = threadIdx.x >> 8;
    const int col  = threadIdx.x & 255;
    const int chunk = blockIdx.y * 4 + sub;

    int lo = 0, hi = n_tok;
    while (lo < hi) { int m = (lo + hi) >> 1; if (seg[m] < gseg) lo = m + 1; else hi = m; }
    const int s = lo;
    lo = s; hi = n_tok;
    while (lo < hi) { int m = (lo + hi) >> 1; if (seg[m] < gseg + 1) lo = m + 1; else hi = m; }
    const int e = lo;

    const int len = e - s;
    const int L = (len + PCHUNK - 1) / PCHUNK;
    const int cs = s + chunk * L;
    const int ce = min(cs + L, e);

    float a0 = 0.f, a1 = 0.f, a2 = 0.f, a3 = 0.f;
    int t = cs;
    for (; t + 4 <= ce; t += 4) {
        a0 += S[(size_t)(t + 0) * DOUT + col];
        a1 += S[(size_t)(t + 1) * DOUT + col];
        a2 += S[(size_t)(t + 2) * DOUT + col];
        a3 += S[(size_t)(t + 3) * DOUT + col];
    }
    float acc = (a0 + a1) + (a2 + a3);
    for (; t < ce; t++) acc += S[(size_t)t * DOUT + col];
    P[((size_t)gseg * PCHUNK + chunk) * DOUT + col] = acc;
}

__global__ void __launch_bounds__(256)
pool_final(const float* __restrict__ P, float* __restrict__ out)
{
    const int gseg = blockIdx.x, col = threadIdx.x;
    float acc = 0.f;
    #pragma unroll
    for (int c = 0; c < PCHUNK; c++)
        acc += P[((size_t)gseg * PCHUNK + c) * DOUT + col];
    out[(size_t)gseg * DOUT + col] = acc;
}

// ---------------- launch ----------------
extern "C" void kernel_launch(void* const* d_in, const int* in_sizes, int n_in,
                              void* d_out, int out_size)
{
    const float* hidden   = (const float*)d_in[0];
    const float* W1       = (const float*)d_in[1];
    const float* b1       = (const float*)d_in[2];
    const float* W2       = (const float*)d_in[3];
    const float* b2       = (const float*)d_in[4];
    const int*   flat_idx = (const int*)d_in[5];
    const int*   seg      = (const int*)d_in[6];
    float*       out      = (float*)d_out;

    const int n_tok = in_sizes[5];
    const int n_img = out_size / DOUT;
    const int mpad  = ((n_tok + 127) / 128) * 128;

    __half *xh, *w1h, *w2h, *hh;
    float *sbuf, *pbuf;
    cudaGetSymbolAddress((void**)&xh,  g_X);
    cudaGetSymbolAddress((void**)&w1h, g_W1h);
    cudaGetSymbolAddress((void**)&w2h, g_W2h);
    cudaGetSymbolAddress((void**)&hh,  g_H);
    cudaGetSymbolAddress((void**)&sbuf, g_S);
    cudaGetSymbolAddress((void**)&pbuf, g_P);

    cudaFuncSetAttribute(mma_gemm<HDIM, true>,
                         cudaFuncAttributeMaxDynamicSharedMemorySize, GEMM_SMEM);
    cudaFuncSetAttribute(mma_gemm<DMID, false>,
                         cudaFuncAttributeMaxDynamicSharedMemorySize, GEMM_SMEM);

    // 1) conversions
    {
        long long t4 = (long long)mpad * HDIM / 4;
        conv_fp16<<<(unsigned)((t4 + 255) / 256), 256>>>(hidden, flat_idx, n_tok, t4, HDIM, xh);
        long long w1t = (long long)DMID * HDIM / 4;
        conv_fp16<<<(unsigned)((w1t + 255) / 256), 256>>>(W1, nullptr, DMID, w1t, HDIM, w1h);
        long long w2t = (long long)DOUT * DMID / 4;
        conv_fp16<<<(unsigned)((w2t + 255) / 256), 256>>>(W2, nullptr, DOUT, w2t, DMID, w2h);
    }
    // 2) GEMM1 + bias + mish -> H (fp16)
    {
        dim3 g(DMID / 256, mpad / 128);
        mma_gemm<HDIM, true><<<g, 512, GEMM_SMEM>>>(xh, w1h, b1, hh, nullptr, DMID);
    }
    // 3) GEMM2 + bias -> S (fp32)
    {
        dim3 g(DOUT / 256, mpad / 128);
        mma_gemm<DMID, false><<<g, 512, GEMM_SMEM>>>(hh, w2h, b2, nullptr, sbuf, DOUT);
    }
    // 4) pooling (2-phase deterministic)
    {
        dim3 gp(n_img, PCHUNK / 4);
        pool_partial<<<gp, 1024>>>(sbuf, seg, n_tok, pbuf);
        pool_final<<<n_img, 256>>>(pbuf, out);
    }
}